// round 12
// baseline (speedup 1.0000x reference)
#include <cuda_runtime.h>
#include <cuda_bf16.h>
#include <cuda_fp16.h>
#include <math.h>

#define B_SZ   4
#define T_LEN  2048
#define S_LEN  4096
#define DIM    256
#define HEADS  8
#define DHEAD  32
#define HID    256
#define QSCALE 0.25505567633920995f   // 32^-0.5 * log2(e)

// ---------------- scratch (no allocation allowed) ----------------
__device__ float  g_q [B_SZ * T_LEN * HID];
__device__ __half g_kh[B_SZ * HEADS * S_LEN * DHEAD];   // K fp16, permuted cols, [b][h][s][32]
__device__ __half g_vt[B_SZ * HEADS * DHEAD * S_LEN];   // V fp16, transposed [b][h][d][s]
__device__ float  g_ao[B_SZ * T_LEN * HID];

// ---------------- helpers ----------------
__device__ __forceinline__ float tf32r(float x) {
    unsigned int u;
    asm("cvt.rna.tf32.f32 %0, %1;" : "=r"(u) : "f"(x));
    return __uint_as_float(u);
}
__device__ __forceinline__ unsigned tf32u(float x) {
    unsigned int u;
    asm("cvt.rna.tf32.f32 %0, %1;" : "=r"(u) : "f"(x));
    return u;
}
__device__ __forceinline__ unsigned packh2(float lo, float hi) {
    __half2 h = __floats2half2_rn(lo, hi);
    return *(unsigned*)&h;
}

__device__ __forceinline__ void mma_tf32(float* c,
                                         unsigned a0, unsigned a1, unsigned a2, unsigned a3,
                                         unsigned b0, unsigned b1) {
    asm volatile(
        "mma.sync.aligned.m16n8k8.row.col.f32.tf32.tf32.f32 "
        "{%0,%1,%2,%3}, {%4,%5,%6,%7}, {%8,%9}, {%0,%1,%2,%3};"
        : "+f"(c[0]), "+f"(c[1]), "+f"(c[2]), "+f"(c[3])
        : "r"(a0), "r"(a1), "r"(a2), "r"(a3), "r"(b0), "r"(b1));
}
__device__ __forceinline__ void mma_f16(float* c,
                                        unsigned a0, unsigned a1, unsigned a2, unsigned a3,
                                        unsigned b0, unsigned b1) {
    asm volatile(
        "mma.sync.aligned.m16n8k16.row.col.f32.f16.f16.f32 "
        "{%0,%1,%2,%3}, {%4,%5,%6,%7}, {%8,%9}, {%0,%1,%2,%3};"
        : "+f"(c[0]), "+f"(c[1]), "+f"(c[2]), "+f"(c[3])
        : "r"(a0), "r"(a1), "r"(a2), "r"(a3), "r"(b0), "r"(b1));
}

__device__ __forceinline__ void cp16(void* smem_ptr, const void* gmem_ptr) {
    unsigned s = (unsigned)__cvta_generic_to_shared(smem_ptr);
    asm volatile("cp.async.cg.shared.global [%0], [%1], 16;" :: "r"(s), "l"(gmem_ptr));
}
#define CP_COMMIT() asm volatile("cp.async.commit_group;")
#define CP_WAIT(n)  asm volatile("cp.async.wait_group %0;" :: "n"(n))

// K column permutation for fp16 m16n8k16 B-frags
__device__ __forceinline__ int permK16(int d) {
    const int kb = d >> 4, dl = d & 15;
    return kb * 16 + ((dl & 7) >> 1) * 4 + ((dl >> 3) << 1) + (dl & 1);
}

// fast exp2 on fma/alu pipes (no MUFU). rel err <= ~4e-5.
__device__ __forceinline__ float fexp2(float x) {
    x = fmaxf(x, -126.f);
    float t = x + 12582912.f;          // 2^23 + 2^22 magic (rint)
    float n = t - 12582912.f;
    float f = x - n;                   // f in [-0.5, 0.5]
    float p = 0.0096181f;
    p = p * f + 0.0554906f;
    p = p * f + 0.2401597f;
    p = p * f + 0.6931472f;
    p = p * f + 1.0f;
    return __int_as_float(__float_as_int(p) + (__float_as_int(t) << 23));
}

// ---------------- tf32 GEMM, cp.async double-buffered ----------------
// MODE: 0 = plain fp32 store, 1 = KV store (K fp16+permK16 -> kh; V fp16 transposed -> vt), 2 = +bias
#define AS2 36
#define WS2 72
#define A_BUF (128 * AS2)
#define W_BUF (32 * WS2)

template<int MODE>
__global__ void gemm_tc_kernel(const float* __restrict__ A,
                               const float* __restrict__ W,
                               const float* __restrict__ bias,
                               float* __restrict__ C,
                               __half* __restrict__ kh,
                               __half* __restrict__ vt,
                               int M, int N, int K) {
    extern __shared__ float sg[];
    float* Asm = sg;
    float* Wsm = sg + 2 * A_BUF;

    const int tid  = threadIdx.x;
    const int warp = tid >> 5;
    const int lane = tid & 31;
    const int g    = lane >> 2;
    const int qd   = lane & 3;
    const int m0 = blockIdx.y * 128;
    const int n0 = blockIdx.x * 64;
    const int rm = (warp & 3) * 32;
    const int cn = (warp >> 2) * 32;

    const int a_row = tid >> 3, a_seg = (tid & 7) * 4;
    const int w_row = tid >> 4, w_seg = (tid & 15) * 4;

    float acc[2][4][4];
    #pragma unroll
    for (int mi = 0; mi < 2; mi++)
        #pragma unroll
        for (int ni = 0; ni < 4; ni++)
            #pragma unroll
            for (int i = 0; i < 4; i++) acc[mi][ni][i] = 0.f;

    auto load_tiles = [&](int buf, int k0) {
        float* Ab = Asm + buf * A_BUF;
        float* Wb = Wsm + buf * W_BUF;
        #pragma unroll
        for (int p = 0; p < 4; p++) {
            int r = p * 32 + a_row;
            cp16(&Ab[r * AS2 + a_seg], &A[(size_t)(m0 + r) * K + k0 + a_seg]);
        }
        #pragma unroll
        for (int p = 0; p < 2; p++) {
            int r = p * 16 + w_row;
            cp16(&Wb[r * WS2 + w_seg], &W[(size_t)(k0 + r) * N + n0 + w_seg]);
        }
    };

    const int n_iter = K / 32;
    load_tiles(0, 0);
    CP_COMMIT();

    for (int it = 0; it < n_iter; it++) {
        if (it + 1 < n_iter) {
            load_tiles((it + 1) & 1, (it + 1) * 32);
            CP_COMMIT();
            CP_WAIT(1);
        } else {
            CP_WAIT(0);
        }
        __syncthreads();

        const float* Ab = Asm + (it & 1) * A_BUF;
        const float* Wb = Wsm + (it & 1) * W_BUF;

        #pragma unroll
        for (int ks = 0; ks < 4; ks++) {
            const int kc = ks * 8;
            unsigned ah[2][4], al[2][4];
            #pragma unroll
            for (int mi = 0; mi < 2; mi++) {
                const int r = rm + mi * 16 + g;
                float r0 = Ab[(r    ) * AS2 + kc + qd    ];
                float r1 = Ab[(r + 8) * AS2 + kc + qd    ];
                float r2 = Ab[(r    ) * AS2 + kc + qd + 4];
                float r3 = Ab[(r + 8) * AS2 + kc + qd + 4];
                float h0 = tf32r(r0), h1 = tf32r(r1), h2 = tf32r(r2), h3 = tf32r(r3);
                ah[mi][0] = __float_as_uint(h0); al[mi][0] = tf32u(r0 - h0);
                ah[mi][1] = __float_as_uint(h1); al[mi][1] = tf32u(r1 - h1);
                ah[mi][2] = __float_as_uint(h2); al[mi][2] = tf32u(r2 - h2);
                ah[mi][3] = __float_as_uint(h3); al[mi][3] = tf32u(r3 - h3);
            }
            #pragma unroll
            for (int ni = 0; ni < 4; ni++) {
                const int n = cn + ni * 8 + g;
                unsigned b0 = tf32u(Wb[(kc + qd    ) * WS2 + n]);
                unsigned b1 = tf32u(Wb[(kc + qd + 4) * WS2 + n]);
                #pragma unroll
                for (int mi = 0; mi < 2; mi++) {
                    mma_tf32(acc[mi][ni], ah[mi][0], ah[mi][1], ah[mi][2], ah[mi][3], b0, b1);
                    mma_tf32(acc[mi][ni], al[mi][0], al[mi][1], al[mi][2], al[mi][3], b0, b1);
                }
            }
        }
        __syncthreads();
    }

    #pragma unroll
    for (int mi = 0; mi < 2; mi++) {
        const int mrow = m0 + rm + mi * 16 + g;
        const size_t r0 = (size_t)mrow * N;
        const size_t r1 = r0 + (size_t)8 * N;
        #pragma unroll
        for (int ni = 0; ni < 4; ni++) {
            const int col = n0 + cn + ni * 8 + 2 * qd;
            if (MODE == 1) {
                const int bb = mrow >> 12;              // S_LEN = 4096
                const int s  = mrow & (S_LEN - 1);
                #pragma unroll
                for (int c2 = 0; c2 < 2; c2++) {
                    const int c = col + c2;
                    const int d = c & 31;
                    if (c < HID) {
                        const int h = c >> 5;
                        const size_t base =
                            ((size_t)(bb * HEADS + h) * S_LEN + s) * DHEAD + permK16(d);
                        kh[base]             = __float2half(acc[mi][ni][0 + c2]);
                        kh[base + 8 * DHEAD] = __float2half(acc[mi][ni][2 + c2]);
                    } else {
                        const int h = (c - HID) >> 5;
                        const size_t base = ((size_t)(bb * HEADS + h) * DHEAD + d) * S_LEN;
                        vt[base + s]     = __float2half(acc[mi][ni][0 + c2]);
                        vt[base + s + 8] = __float2half(acc[mi][ni][2 + c2]);
                    }
                }
            } else {
                float b0v = 0.f, b1v = 0.f;
                if (MODE == 2) { b0v = bias[col]; b1v = bias[col + 1]; }
                *(float2*)&C[r0 + col] = make_float2(acc[mi][ni][0] + b0v, acc[mi][ni][1] + b1v);
                *(float2*)&C[r1 + col] = make_float2(acc[mi][ni][2] + b0v, acc[mi][ni][3] + b1v);
            }
        }
    }
}

// ---------------- tensor-core flash attention (all-fp16 MMA) ----------------
#define QS 36
#define KS16 48
#define VTS 72
#define K_BUF16 (64 * KS16)
#define VT_BUF  (32 * VTS)

__global__ void __launch_bounds__(128, 5)
attn_tc_kernel(const float* __restrict__ q,
               const __half* __restrict__ kh,
               const __half* __restrict__ vt,
               float* __restrict__ ao) {
    extern __shared__ char smraw[];
    __half* Ksh = (__half*)smraw;
    __half* Vsh = (__half*)(smraw + 2 * K_BUF16 * 2);
    float*  Qst = (float*)(smraw + 2 * K_BUF16 * 2 + 2 * VT_BUF * 2);

    const int b    = blockIdx.z;
    const int h    = blockIdx.y;
    const int t0   = blockIdx.x * 64;
    const int tid  = threadIdx.x;
    const int warp = tid >> 5;
    const int lane = tid & 31;
    const int g    = lane >> 2;
    const int qd   = lane & 3;
    const int prow = warp * 16 + g;

    const __half* khbase = kh + ((size_t)(b * HEADS + h) * S_LEN) * DHEAD;
    const __half* vtbase = vt + ((size_t)(b * HEADS + h) * DHEAD) * S_LEN;
    const int lrow = tid >> 3, lseg = (tid & 7) * 4;
    const int krow = tid >> 2, kseg = (tid & 3);
    const int vrow = tid >> 2, vseg = (tid & 3);

    {
        const float* qbase = q + ((size_t)(b * T_LEN + t0)) * HID + h * DHEAD;
        #pragma unroll
        for (int p = 0; p < 4; p++) {
            int r = p * 16 + lrow;
            cp16(&Qst[r * QS + lseg], &qbase[(size_t)r * HID + lseg]);
        }
        CP_COMMIT();
        CP_WAIT(0);
        __syncthreads();
    }

    unsigned qh[2][4], ql[2][4];
    #pragma unroll
    for (int ks = 0; ks < 2; ks++) {
        const int kb = ks * 16;
        float2 x0 = *(const float2*)&Qst[(prow    ) * QS + kb + 2 * qd    ];
        float2 x1 = *(const float2*)&Qst[(prow + 8) * QS + kb + 2 * qd    ];
        float2 x2 = *(const float2*)&Qst[(prow    ) * QS + kb + 2 * qd + 8];
        float2 x3 = *(const float2*)&Qst[(prow + 8) * QS + kb + 2 * qd + 8];
        float2 xs[4] = {x0, x1, x2, x3};
        #pragma unroll
        for (int i = 0; i < 4; i++) {
            float ax = xs[i].x * QSCALE, ay = xs[i].y * QSCALE;
            __half hx = __float2half(ax), hy = __float2half(ay);
            __half2 H = __halves2half2(hx, hy);
            qh[ks][i] = *(unsigned*)&H;
            ql[ks][i] = packh2(ax - __half2float(hx), ay - __half2float(hy));
        }
    }

    float m0 = -1e30f, m1 = -1e30f;
    float l0 = 0.f,    l1 = 0.f;
    float O[4][4];
    #pragma unroll
    for (int j = 0; j < 4; j++)
        #pragma unroll
        for (int i = 0; i < 4; i++) O[j][i] = 0.f;

    auto load_kv = [&](int buf, int s0) {
        __half* Kb = Ksh + buf * K_BUF16;
        __half* Vb = Vsh + buf * VT_BUF;
        #pragma unroll
        for (int p = 0; p < 2; p++) {
            int r = p * 32 + krow;
            cp16(&Kb[r * KS16 + kseg * 8], khbase + (size_t)(s0 + r) * DHEAD + kseg * 8);
        }
        #pragma unroll
        for (int p = 0; p < 2; p++) {
            int seg = vseg + p * 4;
            cp16(&Vb[vrow * VTS + seg * 8], vtbase + (size_t)vrow * S_LEN + s0 + seg * 8);
        }
    };

    const int n_chunks = S_LEN / 64;
    load_kv(0, 0);
    CP_COMMIT();

    for (int it = 0; it < n_chunks; it++) {
        if (it + 1 < n_chunks) {
            load_kv((it + 1) & 1, (it + 1) * 64);
            CP_COMMIT();
            CP_WAIT(1);
        } else {
            CP_WAIT(0);
        }
        __syncthreads();

        const __half* Kb = Ksh + (it & 1) * K_BUF16;
        const __half* Vb = Vsh + (it & 1) * VT_BUF;

        float sacc[8][4];
        #pragma unroll
        for (int j = 0; j < 8; j++)
            #pragma unroll
            for (int i = 0; i < 4; i++) sacc[j][i] = 0.f;

        #pragma unroll
        for (int ks = 0; ks < 2; ks++) {
            const int ko = ks * 16 + qd * 4;
            #pragma unroll
            for (int j = 0; j < 8; j++) {
                uint2 kk = *(const uint2*)&Kb[(j * 8 + g) * KS16 + ko];
                mma_f16(sacc[j], qh[ks][0], qh[ks][1], qh[ks][2], qh[ks][3], kk.x, kk.y);
                mma_f16(sacc[j], ql[ks][0], ql[ks][1], ql[ks][2], ql[ks][3], kk.x, kk.y);
            }
        }

        // ---- online softmax (exp2 domain, FMA-pipe fexp2)
        float mx0 = -1e30f, mx1 = -1e30f;
        #pragma unroll
        for (int j = 0; j < 8; j++) {
            mx0 = fmaxf(mx0, fmaxf(sacc[j][0], sacc[j][1]));
            mx1 = fmaxf(mx1, fmaxf(sacc[j][2], sacc[j][3]));
        }
        #pragma unroll
        for (int off = 1; off < 4; off <<= 1) {
            mx0 = fmaxf(mx0, __shfl_xor_sync(0xffffffffu, mx0, off));
            mx1 = fmaxf(mx1, __shfl_xor_sync(0xffffffffu, mx1, off));
        }
        const float mn0 = fmaxf(m0, mx0);
        const float mn1 = fmaxf(m1, mx1);
        const float c0  = fexp2(m0 - mn0);
        const float c1  = fexp2(m1 - mn1);
        m0 = mn0; m1 = mn1;

        float ls0 = 0.f, ls1 = 0.f;
        #pragma unroll
        for (int j = 0; j < 8; j++) {
            sacc[j][0] = fexp2(sacc[j][0] - mn0);
            sacc[j][1] = fexp2(sacc[j][1] - mn0);
            sacc[j][2] = fexp2(sacc[j][2] - mn1);
            sacc[j][3] = fexp2(sacc[j][3] - mn1);
            ls0 += sacc[j][0] + sacc[j][1];
            ls1 += sacc[j][2] + sacc[j][3];
        }
        #pragma unroll
        for (int off = 1; off < 4; off <<= 1) {
            ls0 += __shfl_xor_sync(0xffffffffu, ls0, off);
            ls1 += __shfl_xor_sync(0xffffffffu, ls1, off);
        }
        l0 = l0 * c0 + ls0;
        l1 = l1 * c1 + ls1;
        #pragma unroll
        for (int j = 0; j < 4; j++) {
            O[j][0] *= c0; O[j][1] *= c0;
            O[j][2] *= c1; O[j][3] *= c1;
        }

        // ---- O += P @ V
        #pragma unroll
        for (int kb = 0; kb < 4; kb++) {
            unsigned a0 = packh2(sacc[2*kb    ][0], sacc[2*kb    ][1]);
            unsigned a1 = packh2(sacc[2*kb    ][2], sacc[2*kb    ][3]);
            unsigned a2 = packh2(sacc[2*kb + 1][0], sacc[2*kb + 1][1]);
            unsigned a3 = packh2(sacc[2*kb + 1][2], sacc[2*kb + 1][3]);
            const int sc = kb * 16 + 2 * qd;
            #pragma unroll
            for (int j = 0; j < 4; j++) {
                const __half* vr = Vb + (j * 8 + g) * VTS;
                unsigned b0 = *(const unsigned*)&vr[sc];
                unsigned b1 = *(const unsigned*)&vr[sc + 8];
                mma_f16(O[j], a0, a1, a2, a3, b0, b1);
            }
        }
        __syncthreads();
    }

    const float inv0 = 1.f / l0;
    const float inv1 = 1.f / l1;
    const size_t row0 = (size_t)(b * T_LEN + t0 + prow) * HID + h * DHEAD;
    const size_t row1 = row0 + (size_t)8 * HID;
    #pragma unroll
    for (int j = 0; j < 4; j++) {
        const int d0 = j * 8 + 2 * qd;
        *(float2*)&ao[row0 + d0] = make_float2(O[j][0] * inv0, O[j][1] * inv0);
        *(float2*)&ao[row1 + d0] = make_float2(O[j][2] * inv1, O[j][3] * inv1);
    }
}

// ---------------- launch ----------------
extern "C" void kernel_launch(void* const* d_in, const int* in_sizes, int n_in,
                              void* d_out, int out_size) {
    const float* x    = (const float*)d_in[0];
    const float* ctx  = (const float*)d_in[1];
    const float* w_q  = (const float*)d_in[2];
    const float* w_kv = (const float*)d_in[3];
    const float* w_o  = (const float*)d_in[4];
    const float* b_o  = (const float*)d_in[5];
    float* out = (float*)d_out;

    float*  q  = nullptr; cudaGetSymbolAddress((void**)&q,  g_q);
    __half* kh = nullptr; cudaGetSymbolAddress((void**)&kh, g_kh);
    __half* vt = nullptr; cudaGetSymbolAddress((void**)&vt, g_vt);
    float*  ao = nullptr; cudaGetSymbolAddress((void**)&ao, g_ao);

    const int MQ = B_SZ * T_LEN;   // 8192
    const int MK = B_SZ * S_LEN;   // 16384

    const int gemm_smem = (2 * A_BUF + 2 * W_BUF) * sizeof(float);
    const int attn_smem = 2 * K_BUF16 * 2 + 2 * VT_BUF * 2 + 64 * QS * 4;   // 30720 B

    cudaFuncSetAttribute(gemm_tc_kernel<0>,
                         cudaFuncAttributeMaxDynamicSharedMemorySize, gemm_smem);
    cudaFuncSetAttribute(gemm_tc_kernel<1>,
                         cudaFuncAttributeMaxDynamicSharedMemorySize, gemm_smem);
    cudaFuncSetAttribute(gemm_tc_kernel<2>,
                         cudaFuncAttributeMaxDynamicSharedMemorySize, gemm_smem);
    cudaFuncSetAttribute(attn_tc_kernel,
                         cudaFuncAttributeMaxDynamicSharedMemorySize, attn_smem);

    gemm_tc_kernel<0><<<dim3(HID / 64, MQ / 128), 256, gemm_smem>>>(x, w_q, nullptr, q, nullptr, nullptr, MQ, HID, DIM);
    gemm_tc_kernel<1><<<dim3(2 * HID / 64, MK / 128), 256, gemm_smem>>>(ctx, w_kv, nullptr, nullptr, kh, vt, MK, 2 * HID, DIM);
    attn_tc_kernel<<<dim3(T_LEN / 64, HEADS, B_SZ), 128, attn_smem>>>(q, kh, vt, ao);
    gemm_tc_kernel<2><<<dim3(DIM / 64, MQ / 128), 256, gemm_smem>>>(ao, w_o, b_o, out, nullptr, nullptr, MQ, DIM, HID);
}

// round 13
// speedup vs baseline: 1.3147x; 1.3147x over previous
#include <cuda_runtime.h>
#include <cuda_bf16.h>
#include <cuda_fp16.h>
#include <math.h>

#define B_SZ   4
#define T_LEN  2048
#define S_LEN  4096
#define DIM    256
#define HEADS  8
#define DHEAD  32
#define HID    256
#define QSCALE 0.25505567633920995f   // 32^-0.5 * log2(e)

// ---------------- scratch (no allocation allowed) ----------------
__device__ float  g_q [B_SZ * T_LEN * HID];
__device__ __half g_kh[B_SZ * HEADS * S_LEN * DHEAD];   // K fp16, permuted cols, [b][h][s][32]
__device__ __half g_vt[B_SZ * HEADS * DHEAD * S_LEN];   // V fp16, transposed [b][h][d][s]
__device__ float  g_ao[B_SZ * T_LEN * HID];

// ---------------- helpers ----------------
__device__ __forceinline__ float tf32r(float x) {
    unsigned int u;
    asm("cvt.rna.tf32.f32 %0, %1;" : "=r"(u) : "f"(x));
    return __uint_as_float(u);
}
__device__ __forceinline__ unsigned tf32u(float x) {
    unsigned int u;
    asm("cvt.rna.tf32.f32 %0, %1;" : "=r"(u) : "f"(x));
    return u;
}
__device__ __forceinline__ unsigned packh2(float lo, float hi) {
    __half2 h = __floats2half2_rn(lo, hi);
    return *(unsigned*)&h;
}

__device__ __forceinline__ void mma_tf32(float* c,
                                         unsigned a0, unsigned a1, unsigned a2, unsigned a3,
                                         unsigned b0, unsigned b1) {
    asm volatile(
        "mma.sync.aligned.m16n8k8.row.col.f32.tf32.tf32.f32 "
        "{%0,%1,%2,%3}, {%4,%5,%6,%7}, {%8,%9}, {%0,%1,%2,%3};"
        : "+f"(c[0]), "+f"(c[1]), "+f"(c[2]), "+f"(c[3])
        : "r"(a0), "r"(a1), "r"(a2), "r"(a3), "r"(b0), "r"(b1));
}
__device__ __forceinline__ void mma_f16(float* c,
                                        unsigned a0, unsigned a1, unsigned a2, unsigned a3,
                                        unsigned b0, unsigned b1) {
    asm volatile(
        "mma.sync.aligned.m16n8k16.row.col.f32.f16.f16.f32 "
        "{%0,%1,%2,%3}, {%4,%5,%6,%7}, {%8,%9}, {%0,%1,%2,%3};"
        : "+f"(c[0]), "+f"(c[1]), "+f"(c[2]), "+f"(c[3])
        : "r"(a0), "r"(a1), "r"(a2), "r"(a3), "r"(b0), "r"(b1));
}

__device__ __forceinline__ void cp16(void* smem_ptr, const void* gmem_ptr) {
    unsigned s = (unsigned)__cvta_generic_to_shared(smem_ptr);
    asm volatile("cp.async.cg.shared.global [%0], [%1], 16;" :: "r"(s), "l"(gmem_ptr));
}
#define CP_COMMIT() asm volatile("cp.async.commit_group;")
#define CP_WAIT(n)  asm volatile("cp.async.wait_group %0;" :: "n"(n))

// K column permutation for fp16 m16n8k16 B-frags
__device__ __forceinline__ int permK16(int d) {
    const int kb = d >> 4, dl = d & 15;
    return kb * 16 + ((dl & 7) >> 1) * 4 + ((dl >> 3) << 1) + (dl & 1);
}

// ---------------- tf32 GEMM, cp.async double-buffered ----------------
// MODE: 0 = plain fp32 store, 1 = KV store (K fp16+permK16 -> kh; V fp16 transposed -> vt), 2 = +bias
#define AS2 36
#define WS2 72
#define A_BUF (128 * AS2)
#define W_BUF (32 * WS2)

template<int MODE>
__global__ void gemm_tc_kernel(const float* __restrict__ A,
                               const float* __restrict__ W,
                               const float* __restrict__ bias,
                               float* __restrict__ C,
                               __half* __restrict__ kh,
                               __half* __restrict__ vt,
                               int M, int N, int K) {
    extern __shared__ float sg[];
    float* Asm = sg;
    float* Wsm = sg + 2 * A_BUF;

    const int tid  = threadIdx.x;
    const int warp = tid >> 5;
    const int lane = tid & 31;
    const int g    = lane >> 2;
    const int qd   = lane & 3;
    const int m0 = blockIdx.y * 128;
    const int n0 = blockIdx.x * 64;
    const int rm = (warp & 3) * 32;
    const int cn = (warp >> 2) * 32;

    const int a_row = tid >> 3, a_seg = (tid & 7) * 4;
    const int w_row = tid >> 4, w_seg = (tid & 15) * 4;

    float acc[2][4][4];
    #pragma unroll
    for (int mi = 0; mi < 2; mi++)
        #pragma unroll
        for (int ni = 0; ni < 4; ni++)
            #pragma unroll
            for (int i = 0; i < 4; i++) acc[mi][ni][i] = 0.f;

    auto load_tiles = [&](int buf, int k0) {
        float* Ab = Asm + buf * A_BUF;
        float* Wb = Wsm + buf * W_BUF;
        #pragma unroll
        for (int p = 0; p < 4; p++) {
            int r = p * 32 + a_row;
            cp16(&Ab[r * AS2 + a_seg], &A[(size_t)(m0 + r) * K + k0 + a_seg]);
        }
        #pragma unroll
        for (int p = 0; p < 2; p++) {
            int r = p * 16 + w_row;
            cp16(&Wb[r * WS2 + w_seg], &W[(size_t)(k0 + r) * N + n0 + w_seg]);
        }
    };

    const int n_iter = K / 32;
    load_tiles(0, 0);
    CP_COMMIT();

    for (int it = 0; it < n_iter; it++) {
        if (it + 1 < n_iter) {
            load_tiles((it + 1) & 1, (it + 1) * 32);
            CP_COMMIT();
            CP_WAIT(1);
        } else {
            CP_WAIT(0);
        }
        __syncthreads();

        const float* Ab = Asm + (it & 1) * A_BUF;
        const float* Wb = Wsm + (it & 1) * W_BUF;

        #pragma unroll
        for (int ks = 0; ks < 4; ks++) {
            const int kc = ks * 8;
            unsigned ah[2][4], al[2][4];
            #pragma unroll
            for (int mi = 0; mi < 2; mi++) {
                const int r = rm + mi * 16 + g;
                float r0 = Ab[(r    ) * AS2 + kc + qd    ];
                float r1 = Ab[(r + 8) * AS2 + kc + qd    ];
                float r2 = Ab[(r    ) * AS2 + kc + qd + 4];
                float r3 = Ab[(r + 8) * AS2 + kc + qd + 4];
                float h0 = tf32r(r0), h1 = tf32r(r1), h2 = tf32r(r2), h3 = tf32r(r3);
                ah[mi][0] = __float_as_uint(h0); al[mi][0] = tf32u(r0 - h0);
                ah[mi][1] = __float_as_uint(h1); al[mi][1] = tf32u(r1 - h1);
                ah[mi][2] = __float_as_uint(h2); al[mi][2] = tf32u(r2 - h2);
                ah[mi][3] = __float_as_uint(h3); al[mi][3] = tf32u(r3 - h3);
            }
            #pragma unroll
            for (int ni = 0; ni < 4; ni++) {
                const int n = cn + ni * 8 + g;
                unsigned b0 = tf32u(Wb[(kc + qd    ) * WS2 + n]);
                unsigned b1 = tf32u(Wb[(kc + qd + 4) * WS2 + n]);
                #pragma unroll
                for (int mi = 0; mi < 2; mi++) {
                    mma_tf32(acc[mi][ni], ah[mi][0], ah[mi][1], ah[mi][2], ah[mi][3], b0, b1);
                    mma_tf32(acc[mi][ni], al[mi][0], al[mi][1], al[mi][2], al[mi][3], b0, b1);
                }
            }
        }
        __syncthreads();
    }

    #pragma unroll
    for (int mi = 0; mi < 2; mi++) {
        const int mrow = m0 + rm + mi * 16 + g;
        const size_t r0 = (size_t)mrow * N;
        const size_t r1 = r0 + (size_t)8 * N;
        #pragma unroll
        for (int ni = 0; ni < 4; ni++) {
            const int col = n0 + cn + ni * 8 + 2 * qd;
            if (MODE == 1) {
                const int bb = mrow >> 12;              // S_LEN = 4096
                const int s  = mrow & (S_LEN - 1);
                #pragma unroll
                for (int c2 = 0; c2 < 2; c2++) {
                    const int c = col + c2;
                    const int d = c & 31;
                    if (c < HID) {
                        const int h = c >> 5;
                        const size_t base =
                            ((size_t)(bb * HEADS + h) * S_LEN + s) * DHEAD + permK16(d);
                        kh[base]             = __float2half(acc[mi][ni][0 + c2]);
                        kh[base + 8 * DHEAD] = __float2half(acc[mi][ni][2 + c2]);
                    } else {
                        const int h = (c - HID) >> 5;
                        const size_t base = ((size_t)(bb * HEADS + h) * DHEAD + d) * S_LEN;
                        vt[base + s]     = __float2half(acc[mi][ni][0 + c2]);
                        vt[base + s + 8] = __float2half(acc[mi][ni][2 + c2]);
                    }
                }
            } else {
                float b0v = 0.f, b1v = 0.f;
                if (MODE == 2) { b0v = bias[col]; b1v = bias[col + 1]; }
                *(float2*)&C[r0 + col] = make_float2(acc[mi][ni][0] + b0v, acc[mi][ni][1] + b1v);
                *(float2*)&C[r1 + col] = make_float2(acc[mi][ni][2] + b0v, acc[mi][ni][3] + b1v);
            }
        }
    }
}

// ---------------- tensor-core flash attention (all-fp16 MMA, single-term QK) ----------------
#define QS 36
#define KS16 48
#define VTS 72
#define K_BUF16 (64 * KS16)
#define VT_BUF  (32 * VTS)

__global__ void __launch_bounds__(128, 5)
attn_tc_kernel(const float* __restrict__ q,
               const __half* __restrict__ kh,
               const __half* __restrict__ vt,
               float* __restrict__ ao) {
    extern __shared__ char smraw[];
    __half* Ksh = (__half*)smraw;
    __half* Vsh = (__half*)(smraw + 2 * K_BUF16 * 2);
    float*  Qst = (float*)(smraw + 2 * K_BUF16 * 2 + 2 * VT_BUF * 2);

    const int b    = blockIdx.z;
    const int h    = blockIdx.y;
    const int t0   = blockIdx.x * 64;
    const int tid  = threadIdx.x;
    const int warp = tid >> 5;
    const int lane = tid & 31;
    const int g    = lane >> 2;
    const int qd   = lane & 3;
    const int prow = warp * 16 + g;

    const __half* khbase = kh + ((size_t)(b * HEADS + h) * S_LEN) * DHEAD;
    const __half* vtbase = vt + ((size_t)(b * HEADS + h) * DHEAD) * S_LEN;
    const int lrow = tid >> 3, lseg = (tid & 7) * 4;
    const int krow = tid >> 2, kseg = (tid & 3);
    const int vrow = tid >> 2, vseg = (tid & 3);

    {
        const float* qbase = q + ((size_t)(b * T_LEN + t0)) * HID + h * DHEAD;
        #pragma unroll
        for (int p = 0; p < 4; p++) {
            int r = p * 16 + lrow;
            cp16(&Qst[r * QS + lseg], &qbase[(size_t)r * HID + lseg]);
        }
        CP_COMMIT();
        CP_WAIT(0);
        __syncthreads();
    }

    unsigned qh[2][4];
    #pragma unroll
    for (int ks = 0; ks < 2; ks++) {
        const int kb = ks * 16;
        float2 x0 = *(const float2*)&Qst[(prow    ) * QS + kb + 2 * qd    ];
        float2 x1 = *(const float2*)&Qst[(prow + 8) * QS + kb + 2 * qd    ];
        float2 x2 = *(const float2*)&Qst[(prow    ) * QS + kb + 2 * qd + 8];
        float2 x3 = *(const float2*)&Qst[(prow + 8) * QS + kb + 2 * qd + 8];
        qh[ks][0] = packh2(x0.x * QSCALE, x0.y * QSCALE);
        qh[ks][1] = packh2(x1.x * QSCALE, x1.y * QSCALE);
        qh[ks][2] = packh2(x2.x * QSCALE, x2.y * QSCALE);
        qh[ks][3] = packh2(x3.x * QSCALE, x3.y * QSCALE);
    }

    float m0 = -1e30f, m1 = -1e30f;
    float l0 = 0.f,    l1 = 0.f;
    float O[4][4];
    #pragma unroll
    for (int j = 0; j < 4; j++)
        #pragma unroll
        for (int i = 0; i < 4; i++) O[j][i] = 0.f;

    auto load_kv = [&](int buf, int s0) {
        __half* Kb = Ksh + buf * K_BUF16;
        __half* Vb = Vsh + buf * VT_BUF;
        #pragma unroll
        for (int p = 0; p < 2; p++) {
            int r = p * 32 + krow;
            cp16(&Kb[r * KS16 + kseg * 8], khbase + (size_t)(s0 + r) * DHEAD + kseg * 8);
        }
        #pragma unroll
        for (int p = 0; p < 2; p++) {
            int seg = vseg + p * 4;
            cp16(&Vb[vrow * VTS + seg * 8], vtbase + (size_t)vrow * S_LEN + s0 + seg * 8);
        }
    };

    const int n_chunks = S_LEN / 64;
    load_kv(0, 0);
    CP_COMMIT();

    for (int it = 0; it < n_chunks; it++) {
        if (it + 1 < n_chunks) {
            load_kv((it + 1) & 1, (it + 1) * 64);
            CP_COMMIT();
            CP_WAIT(1);
        } else {
            CP_WAIT(0);
        }
        __syncthreads();

        const __half* Kb = Ksh + (it & 1) * K_BUF16;
        const __half* Vb = Vsh + (it & 1) * VT_BUF;

        float sacc[8][4];
        #pragma unroll
        for (int j = 0; j < 8; j++)
            #pragma unroll
            for (int i = 0; i < 4; i++) sacc[j][i] = 0.f;

        #pragma unroll
        for (int ks = 0; ks < 2; ks++) {
            const int ko = ks * 16 + qd * 4;
            #pragma unroll
            for (int j = 0; j < 8; j++) {
                uint2 kk = *(const uint2*)&Kb[(j * 8 + g) * KS16 + ko];
                mma_f16(sacc[j], qh[ks][0], qh[ks][1], qh[ks][2], qh[ks][3], kk.x, kk.y);
            }
        }

        // ---- online softmax (exp2 domain, MUFU)
        float mx0 = -1e30f, mx1 = -1e30f;
        #pragma unroll
        for (int j = 0; j < 8; j++) {
            mx0 = fmaxf(mx0, fmaxf(sacc[j][0], sacc[j][1]));
            mx1 = fmaxf(mx1, fmaxf(sacc[j][2], sacc[j][3]));
        }
        #pragma unroll
        for (int off = 1; off < 4; off <<= 1) {
            mx0 = fmaxf(mx0, __shfl_xor_sync(0xffffffffu, mx0, off));
            mx1 = fmaxf(mx1, __shfl_xor_sync(0xffffffffu, mx1, off));
        }
        const float mn0 = fmaxf(m0, mx0);
        const float mn1 = fmaxf(m1, mx1);
        const float c0  = exp2f(m0 - mn0);
        const float c1  = exp2f(m1 - mn1);
        m0 = mn0; m1 = mn1;

        float ls0 = 0.f, ls1 = 0.f;
        #pragma unroll
        for (int j = 0; j < 8; j++) {
            sacc[j][0] = exp2f(sacc[j][0] - mn0);
            sacc[j][1] = exp2f(sacc[j][1] - mn0);
            sacc[j][2] = exp2f(sacc[j][2] - mn1);
            sacc[j][3] = exp2f(sacc[j][3] - mn1);
            ls0 += sacc[j][0] + sacc[j][1];
            ls1 += sacc[j][2] + sacc[j][3];
        }
        #pragma unroll
        for (int off = 1; off < 4; off <<= 1) {
            ls0 += __shfl_xor_sync(0xffffffffu, ls0, off);
            ls1 += __shfl_xor_sync(0xffffffffu, ls1, off);
        }
        l0 = l0 * c0 + ls0;
        l1 = l1 * c1 + ls1;
        #pragma unroll
        for (int j = 0; j < 4; j++) {
            O[j][0] *= c0; O[j][1] *= c0;
            O[j][2] *= c1; O[j][3] *= c1;
        }

        // ---- O += P @ V
        #pragma unroll
        for (int kb = 0; kb < 4; kb++) {
            unsigned a0 = packh2(sacc[2*kb    ][0], sacc[2*kb    ][1]);
            unsigned a1 = packh2(sacc[2*kb    ][2], sacc[2*kb    ][3]);
            unsigned a2 = packh2(sacc[2*kb + 1][0], sacc[2*kb + 1][1]);
            unsigned a3 = packh2(sacc[2*kb + 1][2], sacc[2*kb + 1][3]);
            const int sc = kb * 16 + 2 * qd;
            #pragma unroll
            for (int j = 0; j < 4; j++) {
                const __half* vr = Vb + (j * 8 + g) * VTS;
                unsigned b0 = *(const unsigned*)&vr[sc];
                unsigned b1 = *(const unsigned*)&vr[sc + 8];
                mma_f16(O[j], a0, a1, a2, a3, b0, b1);
            }
        }
        __syncthreads();
    }

    const float inv0 = 1.f / l0;
    const float inv1 = 1.f / l1;
    const size_t row0 = (size_t)(b * T_LEN + t0 + prow) * HID + h * DHEAD;
    const size_t row1 = row0 + (size_t)8 * HID;
    #pragma unroll
    for (int j = 0; j < 4; j++) {
        const int d0 = j * 8 + 2 * qd;
        *(float2*)&ao[row0 + d0] = make_float2(O[j][0] * inv0, O[j][1] * inv0);
        *(float2*)&ao[row1 + d0] = make_float2(O[j][2] * inv1, O[j][3] * inv1);
    }
}

// ---------------- launch ----------------
extern "C" void kernel_launch(void* const* d_in, const int* in_sizes, int n_in,
                              void* d_out, int out_size) {
    const float* x    = (const float*)d_in[0];
    const float* ctx  = (const float*)d_in[1];
    const float* w_q  = (const float*)d_in[2];
    const float* w_kv = (const float*)d_in[3];
    const float* w_o  = (const float*)d_in[4];
    const float* b_o  = (const float*)d_in[5];
    float* out = (float*)d_out;

    float*  q  = nullptr; cudaGetSymbolAddress((void**)&q,  g_q);
    __half* kh = nullptr; cudaGetSymbolAddress((void**)&kh, g_kh);
    __half* vt = nullptr; cudaGetSymbolAddress((void**)&vt, g_vt);
    float*  ao = nullptr; cudaGetSymbolAddress((void**)&ao, g_ao);

    const int MQ = B_SZ * T_LEN;   // 8192
    const int MK = B_SZ * S_LEN;   // 16384

    const int gemm_smem = (2 * A_BUF + 2 * W_BUF) * sizeof(float);
    const int attn_smem = 2 * K_BUF16 * 2 + 2 * VT_BUF * 2 + 64 * QS * 4;   // 30720 B

    cudaFuncSetAttribute(gemm_tc_kernel<0>,
                         cudaFuncAttributeMaxDynamicSharedMemorySize, gemm_smem);
    cudaFuncSetAttribute(gemm_tc_kernel<1>,
                         cudaFuncAttributeMaxDynamicSharedMemorySize, gemm_smem);
    cudaFuncSetAttribute(gemm_tc_kernel<2>,
                         cudaFuncAttributeMaxDynamicSharedMemorySize, gemm_smem);
    cudaFuncSetAttribute(attn_tc_kernel,
                         cudaFuncAttributeMaxDynamicSharedMemorySize, attn_smem);

    gemm_tc_kernel<0><<<dim3(HID / 64, MQ / 128), 256, gemm_smem>>>(x, w_q, nullptr, q, nullptr, nullptr, MQ, HID, DIM);
    gemm_tc_kernel<1><<<dim3(2 * HID / 64, MK / 128), 256, gemm_smem>>>(ctx, w_kv, nullptr, nullptr, kh, vt, MK, 2 * HID, DIM);
    attn_tc_kernel<<<dim3(T_LEN / 64, HEADS, B_SZ), 128, attn_smem>>>(q, kh, vt, ao);
    gemm_tc_kernel<2><<<dim3(DIM / 64, MQ / 128), 256, gemm_smem>>>(ao, w_o, b_o, out, nullptr, nullptr, MQ, DIM, HID);
}

// round 14
// speedup vs baseline: 1.6143x; 1.2279x over previous
#include <cuda_runtime.h>
#include <cuda_bf16.h>
#include <cuda_fp16.h>
#include <math.h>

#define B_SZ   4
#define T_LEN  2048
#define S_LEN  4096
#define DIM    256
#define HEADS  8
#define DHEAD  32
#define HID    256
#define QSCALE 0.25505567633920995f   // 32^-0.5 * log2(e)

// ---------------- scratch (no allocation allowed) ----------------
__device__ float  g_q [B_SZ * T_LEN * HID];
__device__ __half g_kh[B_SZ * HEADS * S_LEN * DHEAD];   // K fp16, k16-perm cols, [b][h][s][32]
__device__ __half g_vt[B_SZ * HEADS * DHEAD * S_LEN];   // V fp16, transposed [b][h][d][s], s k16-perm
__device__ float  g_ao[B_SZ * T_LEN * HID];
__device__ __half g_wqt [HID * DIM];        // w_q^T  [n][k] fp16, k16-perm
__device__ __half g_wkvt[2 * HID * DIM];    // w_kv^T [n][k] fp16, k16-perm

// ---------------- helpers ----------------
__device__ __forceinline__ float tf32r(float x) {
    unsigned int u;
    asm("cvt.rna.tf32.f32 %0, %1;" : "=r"(u) : "f"(x));
    return __uint_as_float(u);
}
__device__ __forceinline__ unsigned tf32u(float x) {
    unsigned int u;
    asm("cvt.rna.tf32.f32 %0, %1;" : "=r"(u) : "f"(x));
    return u;
}
__device__ __forceinline__ unsigned packh2(float lo, float hi) {
    __half2 h = __floats2half2_rn(lo, hi);
    return *(unsigned*)&h;
}

__device__ __forceinline__ void mma_tf32(float* c,
                                         unsigned a0, unsigned a1, unsigned a2, unsigned a3,
                                         unsigned b0, unsigned b1) {
    asm volatile(
        "mma.sync.aligned.m16n8k8.row.col.f32.tf32.tf32.f32 "
        "{%0,%1,%2,%3}, {%4,%5,%6,%7}, {%8,%9}, {%0,%1,%2,%3};"
        : "+f"(c[0]), "+f"(c[1]), "+f"(c[2]), "+f"(c[3])
        : "r"(a0), "r"(a1), "r"(a2), "r"(a3), "r"(b0), "r"(b1));
}
__device__ __forceinline__ void mma_f16(float* c,
                                        unsigned a0, unsigned a1, unsigned a2, unsigned a3,
                                        unsigned b0, unsigned b1) {
    asm volatile(
        "mma.sync.aligned.m16n8k16.row.col.f32.f16.f16.f32 "
        "{%0,%1,%2,%3}, {%4,%5,%6,%7}, {%8,%9}, {%0,%1,%2,%3};"
        : "+f"(c[0]), "+f"(c[1]), "+f"(c[2]), "+f"(c[3])
        : "r"(a0), "r"(a1), "r"(a2), "r"(a3), "r"(b0), "r"(b1));
}

__device__ __forceinline__ void cp16(void* smem_ptr, const void* gmem_ptr) {
    unsigned s = (unsigned)__cvta_generic_to_shared(smem_ptr);
    asm volatile("cp.async.cg.shared.global [%0], [%1], 16;" :: "r"(s), "l"(gmem_ptr));
}
#define CP_COMMIT() asm volatile("cp.async.commit_group;")
#define CP_WAIT(n)  asm volatile("cp.async.wait_group %0;" :: "n"(n))

// k16 fragment permutation: storage position for logical index d (within 16-blocks)
__device__ __forceinline__ int permK16(int d) {
    const int kb = d >> 4, dl = d & 15;
    return kb * 16 + ((dl & 7) >> 1) * 4 + ((dl >> 3) << 1) + (dl & 1);
}
// inverse within a 16-block: logical index for storage position p
__device__ __forceinline__ int invmap16(int p) {
    return ((p >> 2) * 2) + (((p >> 1) & 1) * 8) + (p & 1);
}

// ---------------- weight convert: W [K=256][N] -> Wt [N][256] fp16, k16-perm ----------------
__global__ void conv_w(const float* __restrict__ w, __half* __restrict__ wt, int N) {
    int i = blockIdx.x * 256 + threadIdx.x;
    if (i >= N * 256) return;
    int k = i & 255;
    int n = i >> 8;
    int sk = (k & ~15) | invmap16(k & 15);
    wt[i] = __float2half(w[(size_t)sk * N + n]);
}

// ---------------- fp16 single-term GEMM (q-proj / kv-proj) ----------------
// C = A @ W. A fp32 in smem (converted to fp16 at fragment time), W fp16 [n][k] pre-permuted.
// BM=128, BN=64, BK=32, 256 threads = 8 warps (4 row x 2 col), warp tile 32x32.
// MODE: 0 = fp32 store (q), 1 = kv epilogue (K fp16+permK16 -> kh; V fp16 transposed+permS -> vt)
#define AS3 40                   // A smem stride in floats (160 B; 8g+2qd bank pattern)
#define WH  48                   // W smem stride in halves (96 B; 24g+2qd pattern)
#define A3_BUF (128 * AS3)       // floats
#define WH_BUF (64 * WH)         // halves

template<int MODE>
__global__ void gemm_f16_kernel(const float* __restrict__ A,
                                const __half* __restrict__ Wt,
                                float* __restrict__ C,
                                __half* __restrict__ kh,
                                __half* __restrict__ vt,
                                int M, int N, int K) {
    extern __shared__ char smg[];
    float*  Asm = (float*)smg;                         // 2 * 128*40 floats
    __half* Wsm = (__half*)(smg + 2 * A3_BUF * 4);     // 2 * 64*48 halves

    const int tid  = threadIdx.x;
    const int warp = tid >> 5;
    const int lane = tid & 31;
    const int g    = lane >> 2;
    const int qd   = lane & 3;
    const int m0 = blockIdx.y * 128;
    const int n0 = blockIdx.x * 64;
    const int rm = (warp & 3) * 32;
    const int cn = (warp >> 2) * 32;

    const int a_row = tid >> 3, a_seg = (tid & 7) * 4;   // 32 rows/pass, 4 passes
    const int w_row = tid >> 2, w_seg = (tid & 3) * 8;   // 64 rows, 8 halves/seg

    float acc[2][4][4];
    #pragma unroll
    for (int mi = 0; mi < 2; mi++)
        #pragma unroll
        for (int ni = 0; ni < 4; ni++)
            #pragma unroll
            for (int i = 0; i < 4; i++) acc[mi][ni][i] = 0.f;

    auto load_tiles = [&](int buf, int k0) {
        float*  Ab = Asm + buf * A3_BUF;
        __half* Wb = Wsm + buf * WH_BUF;
        #pragma unroll
        for (int p = 0; p < 4; p++) {
            int r = p * 32 + a_row;
            cp16(&Ab[r * AS3 + a_seg], &A[(size_t)(m0 + r) * K + k0 + a_seg]);
        }
        cp16(&Wb[w_row * WH + w_seg], &Wt[(size_t)(n0 + w_row) * K + k0 + w_seg]);
    };

    const int n_iter = K / 32;   // 8
    load_tiles(0, 0);
    CP_COMMIT();

    for (int it = 0; it < n_iter; it++) {
        if (it + 1 < n_iter) {
            load_tiles((it + 1) & 1, (it + 1) * 32);
            CP_COMMIT();
            CP_WAIT(1);
        } else {
            CP_WAIT(0);
        }
        __syncthreads();

        const float*  Ab = Asm + (it & 1) * A3_BUF;
        const __half* Wb = Wsm + (it & 1) * WH_BUF;

        #pragma unroll
        for (int ks = 0; ks < 2; ks++) {
            const int kb = ks * 16;
            unsigned af[2][4];
            #pragma unroll
            for (int mi = 0; mi < 2; mi++) {
                const int r = rm + mi * 16 + g;
                float2 p0 = *(const float2*)&Ab[(r    ) * AS3 + kb + 2 * qd    ];
                float2 p1 = *(const float2*)&Ab[(r + 8) * AS3 + kb + 2 * qd    ];
                float2 p2 = *(const float2*)&Ab[(r    ) * AS3 + kb + 2 * qd + 8];
                float2 p3 = *(const float2*)&Ab[(r + 8) * AS3 + kb + 2 * qd + 8];
                af[mi][0] = packh2(p0.x, p0.y);
                af[mi][1] = packh2(p1.x, p1.y);
                af[mi][2] = packh2(p2.x, p2.y);
                af[mi][3] = packh2(p3.x, p3.y);
            }
            #pragma unroll
            for (int ni = 0; ni < 4; ni++) {
                const int n = cn + ni * 8 + g;
                uint2 bb = *(const uint2*)&Wb[n * WH + kb + qd * 4];
                #pragma unroll
                for (int mi = 0; mi < 2; mi++)
                    mma_f16(acc[mi][ni], af[mi][0], af[mi][1], af[mi][2], af[mi][3], bb.x, bb.y);
            }
        }
        __syncthreads();
    }

    #pragma unroll
    for (int mi = 0; mi < 2; mi++) {
        const int mrow = m0 + rm + mi * 16 + g;
        const size_t r0 = (size_t)mrow * N;
        const size_t r1 = r0 + (size_t)8 * N;
        #pragma unroll
        for (int ni = 0; ni < 4; ni++) {
            const int col = n0 + cn + ni * 8 + 2 * qd;
            if (MODE == 1) {
                const int bb = mrow >> 12;              // S_LEN = 4096
                const int s  = mrow & (S_LEN - 1);
                const int sg16 = s & ~15;
                const int ps0 = sg16 | permK16(s & 15);         // s%16 = g
                const int ps1 = sg16 | permK16((s & 15) + 8);   // row+8
                #pragma unroll
                for (int c2 = 0; c2 < 2; c2++) {
                    const int c = col + c2;
                    const int d = c & 31;
                    if (c < HID) {
                        const int h = c >> 5;
                        const size_t base =
                            ((size_t)(bb * HEADS + h) * S_LEN + s) * DHEAD + permK16(d);
                        kh[base]             = __float2half(acc[mi][ni][0 + c2]);
                        kh[base + 8 * DHEAD] = __float2half(acc[mi][ni][2 + c2]);
                    } else {
                        const int h = (c - HID) >> 5;
                        const size_t base = ((size_t)(bb * HEADS + h) * DHEAD + d) * S_LEN;
                        vt[base + ps0] = __float2half(acc[mi][ni][0 + c2]);
                        vt[base + ps1] = __float2half(acc[mi][ni][2 + c2]);
                    }
                }
            } else {
                *(float2*)&C[r0 + col] = make_float2(acc[mi][ni][0], acc[mi][ni][1]);
                *(float2*)&C[r1 + col] = make_float2(acc[mi][ni][2], acc[mi][ni][3]);
            }
        }
    }
}

// ---------------- tf32 GEMM (out-proj, 2-term, bias) ----------------
#define AS2 36
#define WS2 72
#define A_BUF (128 * AS2)
#define W_BUF (32 * WS2)

__global__ void gemm_tc_kernel(const float* __restrict__ A,
                               const float* __restrict__ W,
                               const float* __restrict__ bias,
                               float* __restrict__ C,
                               int M, int N, int K) {
    extern __shared__ float sg[];
    float* Asm = sg;
    float* Wsm = sg + 2 * A_BUF;

    const int tid  = threadIdx.x;
    const int warp = tid >> 5;
    const int lane = tid & 31;
    const int g    = lane >> 2;
    const int qd   = lane & 3;
    const int m0 = blockIdx.y * 128;
    const int n0 = blockIdx.x * 64;
    const int rm = (warp & 3) * 32;
    const int cn = (warp >> 2) * 32;

    const int a_row = tid >> 3, a_seg = (tid & 7) * 4;
    const int w_row = tid >> 4, w_seg = (tid & 15) * 4;

    float acc[2][4][4];
    #pragma unroll
    for (int mi = 0; mi < 2; mi++)
        #pragma unroll
        for (int ni = 0; ni < 4; ni++)
            #pragma unroll
            for (int i = 0; i < 4; i++) acc[mi][ni][i] = 0.f;

    auto load_tiles = [&](int buf, int k0) {
        float* Ab = Asm + buf * A_BUF;
        float* Wb = Wsm + buf * W_BUF;
        #pragma unroll
        for (int p = 0; p < 4; p++) {
            int r = p * 32 + a_row;
            cp16(&Ab[r * AS2 + a_seg], &A[(size_t)(m0 + r) * K + k0 + a_seg]);
        }
        #pragma unroll
        for (int p = 0; p < 2; p++) {
            int r = p * 16 + w_row;
            cp16(&Wb[r * WS2 + w_seg], &W[(size_t)(k0 + r) * N + n0 + w_seg]);
        }
    };

    const int n_iter = K / 32;
    load_tiles(0, 0);
    CP_COMMIT();

    for (int it = 0; it < n_iter; it++) {
        if (it + 1 < n_iter) {
            load_tiles((it + 1) & 1, (it + 1) * 32);
            CP_COMMIT();
            CP_WAIT(1);
        } else {
            CP_WAIT(0);
        }
        __syncthreads();

        const float* Ab = Asm + (it & 1) * A_BUF;
        const float* Wb = Wsm + (it & 1) * W_BUF;

        #pragma unroll
        for (int ks = 0; ks < 4; ks++) {
            const int kc = ks * 8;
            unsigned ah[2][4], al[2][4];
            #pragma unroll
            for (int mi = 0; mi < 2; mi++) {
                const int r = rm + mi * 16 + g;
                float r0 = Ab[(r    ) * AS2 + kc + qd    ];
                float r1 = Ab[(r + 8) * AS2 + kc + qd    ];
                float r2 = Ab[(r    ) * AS2 + kc + qd + 4];
                float r3 = Ab[(r + 8) * AS2 + kc + qd + 4];
                float h0 = tf32r(r0), h1 = tf32r(r1), h2 = tf32r(r2), h3 = tf32r(r3);
                ah[mi][0] = __float_as_uint(h0); al[mi][0] = tf32u(r0 - h0);
                ah[mi][1] = __float_as_uint(h1); al[mi][1] = tf32u(r1 - h1);
                ah[mi][2] = __float_as_uint(h2); al[mi][2] = tf32u(r2 - h2);
                ah[mi][3] = __float_as_uint(h3); al[mi][3] = tf32u(r3 - h3);
            }
            #pragma unroll
            for (int ni = 0; ni < 4; ni++) {
                const int n = cn + ni * 8 + g;
                unsigned b0 = tf32u(Wb[(kc + qd    ) * WS2 + n]);
                unsigned b1 = tf32u(Wb[(kc + qd + 4) * WS2 + n]);
                #pragma unroll
                for (int mi = 0; mi < 2; mi++) {
                    mma_tf32(acc[mi][ni], ah[mi][0], ah[mi][1], ah[mi][2], ah[mi][3], b0, b1);
                    mma_tf32(acc[mi][ni], al[mi][0], al[mi][1], al[mi][2], al[mi][3], b0, b1);
                }
            }
        }
        __syncthreads();
    }

    #pragma unroll
    for (int mi = 0; mi < 2; mi++) {
        const size_t r0 = (size_t)(m0 + rm + mi * 16 + g) * N;
        const size_t r1 = r0 + (size_t)8 * N;
        #pragma unroll
        for (int ni = 0; ni < 4; ni++) {
            const int col = n0 + cn + ni * 8 + 2 * qd;
            float b0v = bias[col], b1v = bias[col + 1];
            *(float2*)&C[r0 + col] = make_float2(acc[mi][ni][0] + b0v, acc[mi][ni][1] + b1v);
            *(float2*)&C[r1 + col] = make_float2(acc[mi][ni][2] + b0v, acc[mi][ni][3] + b1v);
        }
    }
}

// ---------------- tensor-core flash attention (all-fp16 MMA, single-term QK) ----------------
#define QS 36
#define KS16 48
#define VTS 80            // halves per Vt smem row (160 B; conflict-free LDS.64)
#define K_BUF16 (64 * KS16)
#define VT_BUF  (32 * VTS)

__global__ void __launch_bounds__(128, 5)
attn_tc_kernel(const float* __restrict__ q,
               const __half* __restrict__ kh,
               const __half* __restrict__ vt,
               float* __restrict__ ao) {
    extern __shared__ char smraw[];
    __half* Ksh = (__half*)smraw;
    __half* Vsh = (__half*)(smraw + 2 * K_BUF16 * 2);
    float*  Qst = (float*)(smraw + 2 * K_BUF16 * 2 + 2 * VT_BUF * 2);

    const int b    = blockIdx.z;
    const int h    = blockIdx.y;
    const int t0   = blockIdx.x * 64;
    const int tid  = threadIdx.x;
    const int warp = tid >> 5;
    const int lane = tid & 31;
    const int g    = lane >> 2;
    const int qd   = lane & 3;
    const int prow = warp * 16 + g;

    const __half* khbase = kh + ((size_t)(b * HEADS + h) * S_LEN) * DHEAD;
    const __half* vtbase = vt + ((size_t)(b * HEADS + h) * DHEAD) * S_LEN;
    const int lrow = tid >> 3, lseg = (tid & 7) * 4;
    const int krow = tid >> 2, kseg = (tid & 3);
    const int vrow = tid >> 2, vseg = (tid & 3);

    {
        const float* qbase = q + ((size_t)(b * T_LEN + t0)) * HID + h * DHEAD;
        #pragma unroll
        for (int p = 0; p < 4; p++) {
            int r = p * 16 + lrow;
            cp16(&Qst[r * QS + lseg], &qbase[(size_t)r * HID + lseg]);
        }
        CP_COMMIT();
        CP_WAIT(0);
        __syncthreads();
    }

    unsigned qh[2][4];
    #pragma unroll
    for (int ks = 0; ks < 2; ks++) {
        const int kb = ks * 16;
        float2 x0 = *(const float2*)&Qst[(prow    ) * QS + kb + 2 * qd    ];
        float2 x1 = *(const float2*)&Qst[(prow + 8) * QS + kb + 2 * qd    ];
        float2 x2 = *(const float2*)&Qst[(prow    ) * QS + kb + 2 * qd + 8];
        float2 x3 = *(const float2*)&Qst[(prow + 8) * QS + kb + 2 * qd + 8];
        qh[ks][0] = packh2(x0.x * QSCALE, x0.y * QSCALE);
        qh[ks][1] = packh2(x1.x * QSCALE, x1.y * QSCALE);
        qh[ks][2] = packh2(x2.x * QSCALE, x2.y * QSCALE);
        qh[ks][3] = packh2(x3.x * QSCALE, x3.y * QSCALE);
    }

    float m0 = -1e30f, m1 = -1e30f;
    float l0 = 0.f,    l1 = 0.f;
    float O[4][4];
    #pragma unroll
    for (int j = 0; j < 4; j++)
        #pragma unroll
        for (int i = 0; i < 4; i++) O[j][i] = 0.f;

    auto load_kv = [&](int buf, int s0) {
        __half* Kb = Ksh + buf * K_BUF16;
        __half* Vb = Vsh + buf * VT_BUF;
        #pragma unroll
        for (int p = 0; p < 2; p++) {
            int r = p * 32 + krow;
            cp16(&Kb[r * KS16 + kseg * 8], khbase + (size_t)(s0 + r) * DHEAD + kseg * 8);
        }
        #pragma unroll
        for (int p = 0; p < 2; p++) {
            int seg = vseg + p * 4;
            cp16(&Vb[vrow * VTS + seg * 8], vtbase + (size_t)vrow * S_LEN + s0 + seg * 8);
        }
    };

    const int n_chunks = S_LEN / 64;
    load_kv(0, 0);
    CP_COMMIT();

    for (int it = 0; it < n_chunks; it++) {
        if (it + 1 < n_chunks) {
            load_kv((it + 1) & 1, (it + 1) * 64);
            CP_COMMIT();
            CP_WAIT(1);
        } else {
            CP_WAIT(0);
        }
        __syncthreads();

        const __half* Kb = Ksh + (it & 1) * K_BUF16;
        const __half* Vb = Vsh + (it & 1) * VT_BUF;

        float sacc[8][4];
        #pragma unroll
        for (int j = 0; j < 8; j++)
            #pragma unroll
            for (int i = 0; i < 4; i++) sacc[j][i] = 0.f;

        #pragma unroll
        for (int ks = 0; ks < 2; ks++) {
            const int ko = ks * 16 + qd * 4;
            #pragma unroll
            for (int j = 0; j < 8; j++) {
                uint2 kk = *(const uint2*)&Kb[(j * 8 + g) * KS16 + ko];
                mma_f16(sacc[j], qh[ks][0], qh[ks][1], qh[ks][2], qh[ks][3], kk.x, kk.y);
            }
        }

        // ---- online softmax (exp2 domain, MUFU)
        float mx0 = -1e30f, mx1 = -1e30f;
        #pragma unroll
        for (int j = 0; j < 8; j++) {
            mx0 = fmaxf(mx0, fmaxf(sacc[j][0], sacc[j][1]));
            mx1 = fmaxf(mx1, fmaxf(sacc[j][2], sacc[j][3]));
        }
        #pragma unroll
        for (int off = 1; off < 4; off <<= 1) {
            mx0 = fmaxf(mx0, __shfl_xor_sync(0xffffffffu, mx0, off));
            mx1 = fmaxf(mx1, __shfl_xor_sync(0xffffffffu, mx1, off));
        }
        const float mn0 = fmaxf(m0, mx0);
        const float mn1 = fmaxf(m1, mx1);
        const float c0  = exp2f(m0 - mn0);
        const float c1  = exp2f(m1 - mn1);
        m0 = mn0; m1 = mn1;

        float ls0 = 0.f, ls1 = 0.f;
        #pragma unroll
        for (int j = 0; j < 8; j++) {
            sacc[j][0] = exp2f(sacc[j][0] - mn0);
            sacc[j][1] = exp2f(sacc[j][1] - mn0);
            sacc[j][2] = exp2f(sacc[j][2] - mn1);
            sacc[j][3] = exp2f(sacc[j][3] - mn1);
            ls0 += sacc[j][0] + sacc[j][1];
            ls1 += sacc[j][2] + sacc[j][3];
        }
        #pragma unroll
        for (int off = 1; off < 4; off <<= 1) {
            ls0 += __shfl_xor_sync(0xffffffffu, ls0, off);
            ls1 += __shfl_xor_sync(0xffffffffu, ls1, off);
        }
        l0 = l0 * c0 + ls0;
        l1 = l1 * c1 + ls1;
        #pragma unroll
        for (int j = 0; j < 4; j++) {
            O[j][0] *= c0; O[j][1] *= c0;
            O[j][2] *= c1; O[j][3] *= c1;
        }

        // ---- O += P @ V : V B-frags as single LDS.64 (s-dim k16-perm)
        #pragma unroll
        for (int kb = 0; kb < 4; kb++) {
            unsigned a0 = packh2(sacc[2*kb    ][0], sacc[2*kb    ][1]);
            unsigned a1 = packh2(sacc[2*kb    ][2], sacc[2*kb    ][3]);
            unsigned a2 = packh2(sacc[2*kb + 1][0], sacc[2*kb + 1][1]);
            unsigned a3 = packh2(sacc[2*kb + 1][2], sacc[2*kb + 1][3]);
            const int so = kb * 16 + qd * 4;
            #pragma unroll
            for (int j = 0; j < 4; j++) {
                uint2 vv = *(const uint2*)&Vb[(j * 8 + g) * VTS + so];
                mma_f16(O[j], a0, a1, a2, a3, vv.x, vv.y);
            }
        }
        __syncthreads();
    }

    const float inv0 = 1.f / l0;
    const float inv1 = 1.f / l1;
    const size_t row0 = (size_t)(b * T_LEN + t0 + prow) * HID + h * DHEAD;
    const size_t row1 = row0 + (size_t)8 * HID;
    #pragma unroll
    for (int j = 0; j < 4; j++) {
        const int d0 = j * 8 + 2 * qd;
        *(float2*)&ao[row0 + d0] = make_float2(O[j][0] * inv0, O[j][1] * inv0);
        *(float2*)&ao[row1 + d0] = make_float2(O[j][2] * inv1, O[j][3] * inv1);
    }
}

// ---------------- launch ----------------
extern "C" void kernel_launch(void* const* d_in, const int* in_sizes, int n_in,
                              void* d_out, int out_size) {
    const float* x    = (const float*)d_in[0];
    const float* ctx  = (const float*)d_in[1];
    const float* w_q  = (const float*)d_in[2];
    const float* w_kv = (const float*)d_in[3];
    const float* w_o  = (const float*)d_in[4];
    const float* b_o  = (const float*)d_in[5];
    float* out = (float*)d_out;

    float*  q   = nullptr; cudaGetSymbolAddress((void**)&q,   g_q);
    __half* kh  = nullptr; cudaGetSymbolAddress((void**)&kh,  g_kh);
    __half* vt  = nullptr; cudaGetSymbolAddress((void**)&vt,  g_vt);
    float*  ao  = nullptr; cudaGetSymbolAddress((void**)&ao,  g_ao);
    __half* wqt = nullptr; cudaGetSymbolAddress((void**)&wqt, g_wqt);
    __half* wkt = nullptr; cudaGetSymbolAddress((void**)&wkt, g_wkvt);

    const int MQ = B_SZ * T_LEN;   // 8192
    const int MK = B_SZ * S_LEN;   // 16384

    const int g16_smem  = 2 * A3_BUF * 4 + 2 * WH_BUF * 2;                 // 53248
    const int gemm_smem = (2 * A_BUF + 2 * W_BUF) * sizeof(float);         // 55296
    const int attn_smem = 2 * K_BUF16 * 2 + 2 * VT_BUF * 2 + 64 * QS * 4;  // 31744

    cudaFuncSetAttribute(gemm_f16_kernel<0>,
                         cudaFuncAttributeMaxDynamicSharedMemorySize, g16_smem);
    cudaFuncSetAttribute(gemm_f16_kernel<1>,
                         cudaFuncAttributeMaxDynamicSharedMemorySize, g16_smem);
    cudaFuncSetAttribute(gemm_tc_kernel,
                         cudaFuncAttributeMaxDynamicSharedMemorySize, gemm_smem);
    cudaFuncSetAttribute(attn_tc_kernel,
                         cudaFuncAttributeMaxDynamicSharedMemorySize, attn_smem);

    // tiny weight converts (fp32 -> fp16 [n][k], k16-perm)
    conv_w<<<(HID * DIM) / 256, 256>>>(w_q, wqt, HID);
    conv_w<<<(2 * HID * DIM) / 256, 256>>>(w_kv, wkt, 2 * HID);

    gemm_f16_kernel<0><<<dim3(HID / 64, MQ / 128), 256, g16_smem>>>(
        x, wqt, q, nullptr, nullptr, MQ, HID, DIM);
    gemm_f16_kernel<1><<<dim3(2 * HID / 64, MK / 128), 256, g16_smem>>>(
        ctx, wkt, nullptr, kh, vt, MK, 2 * HID, DIM);
    attn_tc_kernel<<<dim3(T_LEN / 64, HEADS, B_SZ), 128, attn_smem>>>(q, kh, vt, ao);
    gemm_tc_kernel<<<dim3(DIM / 64, MQ / 128), 256, gemm_smem>>>(ao, w_o, b_o, out, MQ, DIM, HID);
}